// round 12
// baseline (speedup 1.0000x reference)
#include <cuda_runtime.h>

#define N_NODES 100000
#define DD 64
#define E_EDGES 1600000
#define SCAN_BLOCKS 98
#define SCAN_CHUNK 1024   // 256 threads * 4 elements

// Scratch (static device globals — no allocation allowed)
__device__ float g_h1[N_NODES * DD];
__device__ int   g_row[N_NODES + 1];   // CSR row starts (by dst)
__device__ int   g_cur[N_NODES];       // histogram, then cursors
__device__ int   g_srcp[E_EDGES];      // permuted src indices
__device__ int   g_part[SCAN_BLOCKS];  // scan partials
__device__ int   g_is64;               // edge_index dtype flag

// ---------------------------------------------------------------------------
// Detect edge_index dtype. int64 (values < 2^31) -> all odd int32 words zero.
// ---------------------------------------------------------------------------
__global__ void detect_dtype_kernel(const int* __restrict__ ei32) {
    __shared__ int s_or;
    if (threadIdx.x == 0) s_or = 0;
    __syncthreads();
    int v = 0;
    for (int i = threadIdx.x; i < 4096; i += 256)
        v |= ei32[2 * i + 1];
    atomicOr(&s_or, v);
    __syncthreads();
    if (threadIdx.x == 0) g_is64 = (s_or == 0) ? 1 : 0;
}

// ---------------------------------------------------------------------------
// CSR build: zero counters -> histogram over dst -> 3-step exclusive scan ->
// permute src into dst-sorted order.
// ---------------------------------------------------------------------------
__global__ void zero_cur_kernel() {
    int i = blockIdx.x * blockDim.x + threadIdx.x;
    if (i < N_NODES) g_cur[i] = 0;
}

__global__ void hist_kernel(const void* __restrict__ ei_raw) {
    int e = blockIdx.x * blockDim.x + threadIdx.x;
    if (e >= E_EDGES) return;
    int dst = g_is64 ? (int)((const long long*)ei_raw)[E_EDGES + e]
                     : ((const int*)ei_raw)[E_EDGES + e];
    atomicAdd(&g_cur[dst], 1);
}

__global__ void scan1_kernel() {   // per-block totals
    int b = blockIdx.x, t = threadIdx.x;
    int base = b * SCAN_CHUNK + t * 4;
    int s = 0;
    #pragma unroll
    for (int k = 0; k < 4; k++)
        if (base + k < N_NODES) s += g_cur[base + k];
    __shared__ int sh[256];
    sh[t] = s; __syncthreads();
    for (int d = 128; d > 0; d >>= 1) {
        if (t < d) sh[t] += sh[t + d];
        __syncthreads();
    }
    if (t == 0) g_part[b] = sh[0];
}

__global__ void scan2_kernel() {   // exclusive scan of block totals
    int t = threadIdx.x;
    __shared__ int sh[128];
    int v = (t < SCAN_BLOCKS) ? g_part[t] : 0;
    sh[t] = v; __syncthreads();
    for (int d = 1; d < 128; d <<= 1) {
        int u = (t >= d) ? sh[t - d] : 0;
        __syncthreads();
        sh[t] += u;
        __syncthreads();
    }
    if (t < SCAN_BLOCKS) g_part[t] = sh[t] - v;
}

__global__ void scan3_kernel() {   // write row starts + cursors
    int b = blockIdx.x, t = threadIdx.x;
    int base = b * SCAN_CHUNK + t * 4;
    int c[4]; int lsum = 0;
    #pragma unroll
    for (int k = 0; k < 4; k++) {
        c[k] = (base + k < N_NODES) ? g_cur[base + k] : 0;
        lsum += c[k];
    }
    __shared__ int sh[256];
    sh[t] = lsum; __syncthreads();
    for (int d = 1; d < 256; d <<= 1) {
        int u = (t >= d) ? sh[t - d] : 0;
        __syncthreads();
        sh[t] += u;
        __syncthreads();
    }
    int off = g_part[b] + (sh[t] - lsum);
    #pragma unroll
    for (int k = 0; k < 4; k++) {
        if (base + k < N_NODES) {
            g_row[base + k] = off;
            g_cur[base + k] = off;
            off += c[k];
        }
    }
    if (b == 0 && t == 0) g_row[N_NODES] = E_EDGES;
}

__global__ void permute_kernel(const void* __restrict__ ei_raw) {
    int e = blockIdx.x * blockDim.x + threadIdx.x;
    if (e >= E_EDGES) return;
    int src, dst;
    if (g_is64) {
        const long long* ei = (const long long*)ei_raw;
        src = (int)ei[e];
        dst = (int)ei[E_EDGES + e];
    } else {
        const int* ei = (const int*)ei_raw;
        src = ei[e];
        dst = ei[E_EDGES + e];
    }
    int pos = atomicAdd(&g_cur[dst], 1);
    g_srcp[pos] = src;
}

// ---------------------------------------------------------------------------
// Fused layer 1: per 8-node tile, 8 warps gather edge sums (atomic-free,
// 16 lanes x float4, 2-edge ILP, shfl-combine), add (1+eps0)*x into smem,
// then block re-indexes to (64,4) and runs GEMM with W0 rows in registers.
// g_h1 = relu((agg + (1+eps0)*x) @ W0^T)
// ---------------------------------------------------------------------------
__global__ void __launch_bounds__(256, 2) fused_layer1(
        const float* __restrict__ x,
        const float* __restrict__ W0,
        const float* __restrict__ eps0p) {
    int tid = threadIdx.x;
    int tx = tid & 63, ty = tid >> 6;           // GEMM indexing
    int w = tid >> 5, lane = tid & 31;          // gather indexing
    int half = lane >> 4, c = (lane & 15) << 2;

    float4 wr[16];
    const float4* wg = reinterpret_cast<const float4*>(W0 + tx * DD);
    #pragma unroll
    for (int i = 0; i < 16; i++) wr[i] = wg[i];
    float se = 1.0f + *eps0p;

    __shared__ float hs[8][64];
    const unsigned m = 0xffffffffu;

    int ntiles = N_NODES / 8;
    for (int tile = blockIdx.x; tile < ntiles; tile += gridDim.x) {
        int base = tile * 8;
        {   // gather phase: warp w handles node base+w
            int node = base + w;
            int s = g_row[node], e = g_row[node + 1];
            float4 acc = make_float4(0.f, 0.f, 0.f, 0.f);
            for (int j = s + half; j < e; j += 2) {
                int src = __ldg(&g_srcp[j]);
                float4 v = *reinterpret_cast<const float4*>(x + src * DD + c);
                acc.x += v.x; acc.y += v.y; acc.z += v.z; acc.w += v.w;
            }
            acc.x += __shfl_xor_sync(m, acc.x, 16);
            acc.y += __shfl_xor_sync(m, acc.y, 16);
            acc.z += __shfl_xor_sync(m, acc.z, 16);
            acc.w += __shfl_xor_sync(m, acc.w, 16);
            if (half == 0) {
                float4 xv = *reinterpret_cast<const float4*>(x + node * DD + c);
                acc.x += se * xv.x; acc.y += se * xv.y;
                acc.z += se * xv.z; acc.w += se * xv.w;
                *reinterpret_cast<float4*>(&hs[w][c]) = acc;
            }
        }
        __syncthreads();

        {   // GEMM phase
            const float4* h0 = reinterpret_cast<const float4*>(&hs[ty][0]);
            const float4* h1 = reinterpret_cast<const float4*>(&hs[ty + 4][0]);
            float acc0 = 0.f, acc1 = 0.f;
            #pragma unroll
            for (int kk = 0; kk < 16; kk++) {
                float4 wv = wr[kk];
                float4 a = h0[kk];
                float4 b = h1[kk];
                acc0 = fmaf(a.x, wv.x, acc0); acc1 = fmaf(b.x, wv.x, acc1);
                acc0 = fmaf(a.y, wv.y, acc0); acc1 = fmaf(b.y, wv.y, acc1);
                acc0 = fmaf(a.z, wv.z, acc0); acc1 = fmaf(b.z, wv.z, acc1);
                acc0 = fmaf(a.w, wv.w, acc0); acc1 = fmaf(b.w, wv.w, acc1);
            }
            g_h1[(base + ty) * DD + tx]     = fmaxf(acc0, 0.f);
            g_h1[(base + ty + 4) * DD + tx] = fmaxf(acc1, 0.f);
        }
        __syncthreads();
    }
}

// ---------------------------------------------------------------------------
// Fused layer 2 + mix: gather over g_h1, then
// out = 0.5 * ( h1 @ Wm^T + relu((agg + (1+eps1)*h1) @ W1^T) )
// W1 and Wm both in registers; us (GIN input) and hh (h1) tiles in smem.
// ---------------------------------------------------------------------------
__global__ void __launch_bounds__(256, 1) fused_layer2(
        const float* __restrict__ W1,
        const float* __restrict__ eps1p,
        const float* __restrict__ Wm,
        float* __restrict__ out) {
    int tid = threadIdx.x;
    int tx = tid & 63, ty = tid >> 6;
    int w = tid >> 5, lane = tid & 31;
    int half = lane >> 4, c = (lane & 15) << 2;

    float4 wr1[16], wrm[16];
    const float4* wg1 = reinterpret_cast<const float4*>(W1 + tx * DD);
    const float4* wgm = reinterpret_cast<const float4*>(Wm + tx * DD);
    #pragma unroll
    for (int i = 0; i < 16; i++) { wr1[i] = wg1[i]; wrm[i] = wgm[i]; }
    float se = 1.0f + *eps1p;

    __shared__ float us[8][64];
    __shared__ float hh[8][64];
    const unsigned m = 0xffffffffu;

    int ntiles = N_NODES / 8;
    for (int tile = blockIdx.x; tile < ntiles; tile += gridDim.x) {
        int base = tile * 8;
        {   // gather phase over g_h1
            int node = base + w;
            int s = g_row[node], e = g_row[node + 1];
            float4 acc = make_float4(0.f, 0.f, 0.f, 0.f);
            for (int j = s + half; j < e; j += 2) {
                int src = __ldg(&g_srcp[j]);
                float4 v = *reinterpret_cast<const float4*>(g_h1 + src * DD + c);
                acc.x += v.x; acc.y += v.y; acc.z += v.z; acc.w += v.w;
            }
            acc.x += __shfl_xor_sync(m, acc.x, 16);
            acc.y += __shfl_xor_sync(m, acc.y, 16);
            acc.z += __shfl_xor_sync(m, acc.z, 16);
            acc.w += __shfl_xor_sync(m, acc.w, 16);
            if (half == 0) {
                float4 hv = *reinterpret_cast<const float4*>(g_h1 + node * DD + c);
                *reinterpret_cast<float4*>(&hh[w][c]) = hv;
                acc.x += se * hv.x; acc.y += se * hv.y;
                acc.z += se * hv.z; acc.w += se * hv.w;
                *reinterpret_cast<float4*>(&us[w][c]) = acc;
            }
        }
        __syncthreads();

        {   // dual GEMM phase
            const float4* u0 = reinterpret_cast<const float4*>(&us[ty][0]);
            const float4* u1 = reinterpret_cast<const float4*>(&us[ty + 4][0]);
            const float4* q0 = reinterpret_cast<const float4*>(&hh[ty][0]);
            const float4* q1 = reinterpret_cast<const float4*>(&hh[ty + 4][0]);
            float a0 = 0.f, a1 = 0.f, b0 = 0.f, b1 = 0.f;
            #pragma unroll
            for (int kk = 0; kk < 16; kk++) {
                float4 w1v = wr1[kk];
                float4 wmv = wrm[kk];
                float4 ua = u0[kk], ub = u1[kk];
                float4 qa = q0[kk], qb = q1[kk];
                a0 = fmaf(ua.x, w1v.x, a0); a1 = fmaf(ub.x, w1v.x, a1);
                b0 = fmaf(qa.x, wmv.x, b0); b1 = fmaf(qb.x, wmv.x, b1);
                a0 = fmaf(ua.y, w1v.y, a0); a1 = fmaf(ub.y, w1v.y, a1);
                b0 = fmaf(qa.y, wmv.y, b0); b1 = fmaf(qb.y, wmv.y, b1);
                a0 = fmaf(ua.z, w1v.z, a0); a1 = fmaf(ub.z, w1v.z, a1);
                b0 = fmaf(qa.z, wmv.z, b0); b1 = fmaf(qb.z, wmv.z, b1);
                a0 = fmaf(ua.w, w1v.w, a0); a1 = fmaf(ub.w, w1v.w, a1);
                b0 = fmaf(qa.w, wmv.w, b0); b1 = fmaf(qb.w, wmv.w, b1);
            }
            out[(base + ty) * DD + tx]     = 0.5f * (b0 + fmaxf(a0, 0.f));
            out[(base + ty + 4) * DD + tx] = 0.5f * (b1 + fmaxf(a1, 0.f));
        }
        __syncthreads();
    }
}

// ---------------------------------------------------------------------------
// Launch
// ---------------------------------------------------------------------------
extern "C" void kernel_launch(void* const* d_in, const int* in_sizes, int n_in,
                              void* d_out, int out_size) {
    const float* x    = (const float*)d_in[0];
    const void*  ei   = d_in[1];
    const float* W0   = (const float*)d_in[2];
    const float* eps0 = (const float*)d_in[3];
    const float* W1   = (const float*)d_in[4];
    const float* eps1 = (const float*)d_in[5];
    const float* Wm   = (const float*)d_in[6];
    float*       out  = (float*)d_out;

    detect_dtype_kernel<<<1, 256>>>((const int*)ei);

    // CSR build (once; reused by both layers)
    zero_cur_kernel<<<(N_NODES + 255) / 256, 256>>>();
    hist_kernel<<<E_EDGES / 256, 256>>>(ei);
    scan1_kernel<<<SCAN_BLOCKS, 256>>>();
    scan2_kernel<<<1, 128>>>();
    scan3_kernel<<<SCAN_BLOCKS, 256>>>();
    permute_kernel<<<E_EDGES / 256, 256>>>(ei);

    // Fused layers
    fused_layer1<<<296, 256>>>(x, W0, eps0);
    fused_layer2<<<148, 256>>>(W1, eps1, Wm, out);
}

// round 13
// speedup vs baseline: 1.2834x; 1.2834x over previous
#include <cuda_runtime.h>

#define N_NODES 100000
#define DD 64
#define E_EDGES 1600000
#define SCAN_BLOCKS 98
#define SCAN_CHUNK 1024   // 256 threads * 4 elements

// Scratch (static device globals — no allocation allowed)
__device__ float g_agg[N_NODES * DD];
__device__ float g_h1[N_NODES * DD];
__device__ int   g_row[N_NODES + 1];   // CSR row starts (by dst)
__device__ int   g_cur[N_NODES];       // histogram, then cursors
__device__ int   g_srcp[E_EDGES];      // permuted src indices
__device__ int   g_part[SCAN_BLOCKS];  // scan partials
__device__ int   g_is64;               // edge_index dtype flag

// ---------------------------------------------------------------------------
// Detect edge_index dtype. int64 (values < 2^31) -> all odd int32 words zero.
// ---------------------------------------------------------------------------
__global__ void detect_dtype_kernel(const int* __restrict__ ei32) {
    __shared__ int s_or;
    if (threadIdx.x == 0) s_or = 0;
    __syncthreads();
    int v = 0;
    for (int i = threadIdx.x; i < 4096; i += 256)
        v |= ei32[2 * i + 1];
    atomicOr(&s_or, v);
    __syncthreads();
    if (threadIdx.x == 0) g_is64 = (s_or == 0) ? 1 : 0;
}

// ---------------------------------------------------------------------------
// CSR build: zero counters -> histogram over dst -> 3-step exclusive scan ->
// permute src into dst-sorted order.
// ---------------------------------------------------------------------------
__global__ void zero_cur_kernel() {
    int i = blockIdx.x * blockDim.x + threadIdx.x;
    if (i < N_NODES) g_cur[i] = 0;
}

__global__ void hist_kernel(const void* __restrict__ ei_raw) {
    int e = blockIdx.x * blockDim.x + threadIdx.x;
    if (e >= E_EDGES) return;
    int dst = g_is64 ? (int)((const long long*)ei_raw)[E_EDGES + e]
                     : ((const int*)ei_raw)[E_EDGES + e];
    atomicAdd(&g_cur[dst], 1);
}

__global__ void scan1_kernel() {   // per-block totals
    int b = blockIdx.x, t = threadIdx.x;
    int base = b * SCAN_CHUNK + t * 4;
    int s = 0;
    #pragma unroll
    for (int k = 0; k < 4; k++)
        if (base + k < N_NODES) s += g_cur[base + k];
    __shared__ int sh[256];
    sh[t] = s; __syncthreads();
    for (int d = 128; d > 0; d >>= 1) {
        if (t < d) sh[t] += sh[t + d];
        __syncthreads();
    }
    if (t == 0) g_part[b] = sh[0];
}

__global__ void scan2_kernel() {   // exclusive scan of block totals
    int t = threadIdx.x;
    __shared__ int sh[128];
    int v = (t < SCAN_BLOCKS) ? g_part[t] : 0;
    sh[t] = v; __syncthreads();
    for (int d = 1; d < 128; d <<= 1) {
        int u = (t >= d) ? sh[t - d] : 0;
        __syncthreads();
        sh[t] += u;
        __syncthreads();
    }
    if (t < SCAN_BLOCKS) g_part[t] = sh[t] - v;
}

__global__ void scan3_kernel() {   // write row starts + cursors
    int b = blockIdx.x, t = threadIdx.x;
    int base = b * SCAN_CHUNK + t * 4;
    int c[4]; int lsum = 0;
    #pragma unroll
    for (int k = 0; k < 4; k++) {
        c[k] = (base + k < N_NODES) ? g_cur[base + k] : 0;
        lsum += c[k];
    }
    __shared__ int sh[256];
    sh[t] = lsum; __syncthreads();
    for (int d = 1; d < 256; d <<= 1) {
        int u = (t >= d) ? sh[t - d] : 0;
        __syncthreads();
        sh[t] += u;
        __syncthreads();
    }
    int off = g_part[b] + (sh[t] - lsum);
    #pragma unroll
    for (int k = 0; k < 4; k++) {
        if (base + k < N_NODES) {
            g_row[base + k] = off;
            g_cur[base + k] = off;
            off += c[k];
        }
    }
    if (b == 0 && t == 0) g_row[N_NODES] = E_EDGES;
}

__global__ void permute_kernel(const void* __restrict__ ei_raw) {
    int e = blockIdx.x * blockDim.x + threadIdx.x;
    if (e >= E_EDGES) return;
    int src, dst;
    if (g_is64) {
        const long long* ei = (const long long*)ei_raw;
        src = (int)ei[e];
        dst = (int)ei[E_EDGES + e];
    } else {
        const int* ei = (const int*)ei_raw;
        src = ei[e];
        dst = ei[E_EDGES + e];
    }
    int pos = atomicAdd(&g_cur[dst], 1);
    g_srcp[pos] = src;
}

// ---------------------------------------------------------------------------
// Gather aggregation (atomic-free): one warp per node, 12500 blocks for
// massive latency hiding. Lanes split in halves over even/odd edges;
// 2-deep unroll with dual accumulators raises load MLP.
// ---------------------------------------------------------------------------
__global__ void __launch_bounds__(256) gather_kernel(
        const float* __restrict__ xin, int use_h1) {
    int node = (blockIdx.x * blockDim.x + threadIdx.x) >> 5;
    if (node >= N_NODES) return;
    int lane = threadIdx.x & 31;
    int half = lane >> 4;
    int c = (lane & 15) << 2;

    const float* h = use_h1 ? g_h1 : xin;
    int s = g_row[node], e = g_row[node + 1];

    float4 acc = make_float4(0.f, 0.f, 0.f, 0.f);
    float4 acc2 = make_float4(0.f, 0.f, 0.f, 0.f);
    int j = s + half;
    for (; j + 2 < e; j += 4) {
        int s0 = __ldg(&g_srcp[j]);
        int s1 = __ldg(&g_srcp[j + 2]);
        float4 v0 = *reinterpret_cast<const float4*>(h + s0 * DD + c);
        float4 v1 = *reinterpret_cast<const float4*>(h + s1 * DD + c);
        acc.x += v0.x; acc.y += v0.y; acc.z += v0.z; acc.w += v0.w;
        acc2.x += v1.x; acc2.y += v1.y; acc2.z += v1.z; acc2.w += v1.w;
    }
    if (j < e) {
        int s0 = __ldg(&g_srcp[j]);
        float4 v0 = *reinterpret_cast<const float4*>(h + s0 * DD + c);
        acc.x += v0.x; acc.y += v0.y; acc.z += v0.z; acc.w += v0.w;
    }
    acc.x += acc2.x; acc.y += acc2.y; acc.z += acc2.z; acc.w += acc2.w;

    const unsigned m = 0xffffffffu;
    acc.x += __shfl_xor_sync(m, acc.x, 16);
    acc.y += __shfl_xor_sync(m, acc.y, 16);
    acc.z += __shfl_xor_sync(m, acc.z, 16);
    acc.w += __shfl_xor_sync(m, acc.w, 16);
    if (half == 0)
        *reinterpret_cast<float4*>(g_agg + node * DD + c) = acc;
}

// ---------------------------------------------------------------------------
// GEMM kernels: thread owns output column tx; W row in 16 float4 registers.
// Activations staged in smem, read as warp-uniform broadcasts.
// ---------------------------------------------------------------------------
// Layer 1: g_h1 = relu((g_agg + (1+eps0)*x) @ W0^T)
__global__ void __launch_bounds__(256) gin1_kernel(
        const float* __restrict__ x,
        const float* __restrict__ W0,
        const float* __restrict__ eps0p) {
    int tx = threadIdx.x, ty = threadIdx.y;

    float4 wr[16];
    const float4* wg = reinterpret_cast<const float4*>(W0 + tx * DD);
    #pragma unroll
    for (int i = 0; i < 16; i++) wr[i] = wg[i];
    float se = 1.0f + *eps0p;

    __shared__ float hs[8][64];

    int ntiles = N_NODES / 8;
    for (int tile = blockIdx.x; tile < ntiles; tile += gridDim.x) {
        int base = tile * 8;
        #pragma unroll
        for (int r = 0; r < 2; r++) {
            int node = base + ty + r * 4;
            hs[ty + r * 4][tx] = g_agg[node * DD + tx] + se * x[node * DD + tx];
        }
        __syncthreads();

        const float4* h0 = reinterpret_cast<const float4*>(&hs[ty][0]);
        const float4* h1 = reinterpret_cast<const float4*>(&hs[ty + 4][0]);
        float acc0 = 0.f, acc1 = 0.f;
        #pragma unroll
        for (int kk = 0; kk < 16; kk++) {
            float4 w = wr[kk];
            float4 a = h0[kk];
            float4 b = h1[kk];
            acc0 = fmaf(a.x, w.x, acc0); acc1 = fmaf(b.x, w.x, acc1);
            acc0 = fmaf(a.y, w.y, acc0); acc1 = fmaf(b.y, w.y, acc1);
            acc0 = fmaf(a.z, w.z, acc0); acc1 = fmaf(b.z, w.z, acc1);
            acc0 = fmaf(a.w, w.w, acc0); acc1 = fmaf(b.w, w.w, acc1);
        }
        g_h1[(base + ty) * DD + tx]     = fmaxf(acc0, 0.f);
        g_h1[(base + ty + 4) * DD + tx] = fmaxf(acc1, 0.f);
        __syncthreads();
    }
}

// Final (f1+f2 fused, GEMM-only fusion — both phases compute-bound):
// out = 0.5 * ( h1 @ Wm^T + relu((g_agg + (1+eps1)*h1) @ W1^T) )
__global__ void __launch_bounds__(256, 1) final_kernel(
        const float* __restrict__ W1,
        const float* __restrict__ eps1p,
        const float* __restrict__ Wm,
        float* __restrict__ out) {
    int tx = threadIdx.x, ty = threadIdx.y;

    float4 wr1[16], wrm[16];
    const float4* wg1 = reinterpret_cast<const float4*>(W1 + tx * DD);
    const float4* wgm = reinterpret_cast<const float4*>(Wm + tx * DD);
    #pragma unroll
    for (int i = 0; i < 16; i++) { wr1[i] = wg1[i]; wrm[i] = wgm[i]; }
    float se = 1.0f + *eps1p;

    __shared__ float us[8][64];
    __shared__ float hh[8][64];

    int ntiles = N_NODES / 8;
    for (int tile = blockIdx.x; tile < ntiles; tile += gridDim.x) {
        int base = tile * 8;
        #pragma unroll
        for (int r = 0; r < 2; r++) {
            int node = base + ty + r * 4;
            float h = g_h1[node * DD + tx];
            us[ty + r * 4][tx] = g_agg[node * DD + tx] + se * h;
            hh[ty + r * 4][tx] = h;
        }
        __syncthreads();

        const float4* u0 = reinterpret_cast<const float4*>(&us[ty][0]);
        const float4* u1 = reinterpret_cast<const float4*>(&us[ty + 4][0]);
        const float4* q0 = reinterpret_cast<const float4*>(&hh[ty][0]);
        const float4* q1 = reinterpret_cast<const float4*>(&hh[ty + 4][0]);
        float a0 = 0.f, a1 = 0.f, b0 = 0.f, b1 = 0.f;
        #pragma unroll
        for (int kk = 0; kk < 16; kk++) {
            float4 w1v = wr1[kk];
            float4 wmv = wrm[kk];
            float4 ua = u0[kk], ub = u1[kk];
            float4 qa = q0[kk], qb = q1[kk];
            a0 = fmaf(ua.x, w1v.x, a0); a1 = fmaf(ub.x, w1v.x, a1);
            b0 = fmaf(qa.x, wmv.x, b0); b1 = fmaf(qb.x, wmv.x, b1);
            a0 = fmaf(ua.y, w1v.y, a0); a1 = fmaf(ub.y, w1v.y, a1);
            b0 = fmaf(qa.y, wmv.y, b0); b1 = fmaf(qb.y, wmv.y, b1);
            a0 = fmaf(ua.z, w1v.z, a0); a1 = fmaf(ub.z, w1v.z, a1);
            b0 = fmaf(qa.z, wmv.z, b0); b1 = fmaf(qb.z, wmv.z, b1);
            a0 = fmaf(ua.w, w1v.w, a0); a1 = fmaf(ub.w, w1v.w, a1);
            b0 = fmaf(qa.w, wmv.w, b0); b1 = fmaf(qb.w, wmv.w, b1);
        }
        out[(base + ty) * DD + tx]     = 0.5f * (b0 + fmaxf(a0, 0.f));
        out[(base + ty + 4) * DD + tx] = 0.5f * (b1 + fmaxf(a1, 0.f));
        __syncthreads();
    }
}

// ---------------------------------------------------------------------------
// Launch
// ---------------------------------------------------------------------------
extern "C" void kernel_launch(void* const* d_in, const int* in_sizes, int n_in,
                              void* d_out, int out_size) {
    const float* x    = (const float*)d_in[0];
    const void*  ei   = d_in[1];
    const float* W0   = (const float*)d_in[2];
    const float* eps0 = (const float*)d_in[3];
    const float* W1   = (const float*)d_in[4];
    const float* eps1 = (const float*)d_in[5];
    const float* Wm   = (const float*)d_in[6];
    float*       out  = (float*)d_out;

    dim3 gemm_block(64, 4);

    detect_dtype_kernel<<<1, 256>>>((const int*)ei);

    // CSR build (once; reused by both layers)
    zero_cur_kernel<<<(N_NODES + 255) / 256, 256>>>();
    hist_kernel<<<E_EDGES / 256, 256>>>(ei);
    scan1_kernel<<<SCAN_BLOCKS, 256>>>();
    scan2_kernel<<<1, 128>>>();
    scan3_kernel<<<SCAN_BLOCKS, 256>>>();
    permute_kernel<<<E_EDGES / 256, 256>>>(ei);

    // Layer 1
    gather_kernel<<<(N_NODES * 32) / 256, 256>>>(x, 0);
    gin1_kernel<<<1184, gemm_block>>>(x, W0, eps0);

    // Layer 2 + final mix
    gather_kernel<<<(N_NODES * 32) / 256, 256>>>(x, 1);
    final_kernel<<<1184, gemm_block>>>(W1, eps1, Wm, out);
}

// round 16
// speedup vs baseline: 1.2918x; 1.0065x over previous
#include <cuda_runtime.h>

#define N_NODES 100000
#define DD 64
#define E_EDGES 1600000
#define SCAN_BLOCKS 98
#define SCAN_CHUNK 1024   // 256 threads * 4 elements

// Scratch (static device globals — no allocation allowed).
// NOTE: these must only be referenced from DEVICE code; their host-side
// addresses are invalid as kernel arguments.
__device__ float g_y[N_NODES * DD];    // x @ W0^T
__device__ float g_h1[N_NODES * DD];   // layer-1 output
__device__ float g_z[N_NODES * DD];    // h1 @ W1^T
__device__ float g_m[N_NODES * DD];    // h1 @ Wm^T
__device__ int   g_row[N_NODES + 1];   // CSR row starts (by dst)
__device__ int   g_cur[N_NODES];       // histogram, then cursors
__device__ int   g_srcp[E_EDGES];      // permuted src indices
__device__ int   g_part[SCAN_BLOCKS];  // scan partials
__device__ int   g_is64;               // edge_index dtype flag

// ---------------------------------------------------------------------------
// Detect edge_index dtype. int64 (values < 2^31) -> all odd int32 words zero.
// ---------------------------------------------------------------------------
__global__ void detect_dtype_kernel(const int* __restrict__ ei32) {
    __shared__ int s_or;
    if (threadIdx.x == 0) s_or = 0;
    __syncthreads();
    int v = 0;
    for (int i = threadIdx.x; i < 4096; i += 256)
        v |= ei32[2 * i + 1];
    atomicOr(&s_or, v);
    __syncthreads();
    if (threadIdx.x == 0) g_is64 = (s_or == 0) ? 1 : 0;
}

// ---------------------------------------------------------------------------
// CSR build: zero counters -> histogram over dst -> 3-step exclusive scan ->
// permute src into dst-sorted order.
// ---------------------------------------------------------------------------
__global__ void zero_cur_kernel() {
    int i = blockIdx.x * blockDim.x + threadIdx.x;
    if (i < N_NODES) g_cur[i] = 0;
}

__global__ void hist_kernel(const void* __restrict__ ei_raw) {
    int e = blockIdx.x * blockDim.x + threadIdx.x;
    if (e >= E_EDGES) return;
    int dst = g_is64 ? (int)((const long long*)ei_raw)[E_EDGES + e]
                     : ((const int*)ei_raw)[E_EDGES + e];
    atomicAdd(&g_cur[dst], 1);
}

__global__ void scan1_kernel() {   // per-block totals
    int b = blockIdx.x, t = threadIdx.x;
    int base = b * SCAN_CHUNK + t * 4;
    int s = 0;
    #pragma unroll
    for (int k = 0; k < 4; k++)
        if (base + k < N_NODES) s += g_cur[base + k];
    __shared__ int sh[256];
    sh[t] = s; __syncthreads();
    for (int d = 128; d > 0; d >>= 1) {
        if (t < d) sh[t] += sh[t + d];
        __syncthreads();
    }
    if (t == 0) g_part[b] = sh[0];
}

__global__ void scan2_kernel() {   // exclusive scan of block totals
    int t = threadIdx.x;
    __shared__ int sh[128];
    int v = (t < SCAN_BLOCKS) ? g_part[t] : 0;
    sh[t] = v; __syncthreads();
    for (int d = 1; d < 128; d <<= 1) {
        int u = (t >= d) ? sh[t - d] : 0;
        __syncthreads();
        sh[t] += u;
        __syncthreads();
    }
    if (t < SCAN_BLOCKS) g_part[t] = sh[t] - v;
}

__global__ void scan3_kernel() {   // write row starts + cursors
    int b = blockIdx.x, t = threadIdx.x;
    int base = b * SCAN_CHUNK + t * 4;
    int c[4]; int lsum = 0;
    #pragma unroll
    for (int k = 0; k < 4; k++) {
        c[k] = (base + k < N_NODES) ? g_cur[base + k] : 0;
        lsum += c[k];
    }
    __shared__ int sh[256];
    sh[t] = lsum; __syncthreads();
    for (int d = 1; d < 256; d <<= 1) {
        int u = (t >= d) ? sh[t - d] : 0;
        __syncthreads();
        sh[t] += u;
        __syncthreads();
    }
    int off = g_part[b] + (sh[t] - lsum);
    #pragma unroll
    for (int k = 0; k < 4; k++) {
        if (base + k < N_NODES) {
            g_row[base + k] = off;
            g_cur[base + k] = off;
            off += c[k];
        }
    }
    if (b == 0 && t == 0) g_row[N_NODES] = E_EDGES;
}

__global__ void permute_kernel(const void* __restrict__ ei_raw) {
    int e = blockIdx.x * blockDim.x + threadIdx.x;
    if (e >= E_EDGES) return;
    int src, dst;
    if (g_is64) {
        const long long* ei = (const long long*)ei_raw;
        src = (int)ei[e];
        dst = (int)ei[E_EDGES + e];
    } else {
        const int* ei = (const int*)ei_raw;
        src = ei[e];
        dst = ei[E_EDGES + e];
    }
    int pos = atomicAdd(&g_cur[dst], 1);
    g_srcp[pos] = src;
}

// ---------------------------------------------------------------------------
// Plain GEMM over scratch globals, selected by mode (globals referenced only
// in device code):
//   mode 0: g_y = x  @ W^T      (x from harness)
//   mode 1: g_z = g_h1 @ W^T
//   mode 2: g_m = g_h1 @ W^T
// Thread owns output column tx; W row in 16 float4 registers. Activations
// staged in smem, warp-uniform broadcast reads. blockDim (64,4).
// ---------------------------------------------------------------------------
__global__ void __launch_bounds__(256) gemm_kernel(
        const float* __restrict__ xin,
        const float* __restrict__ W,
        int mode) {
    const float* src = (mode == 0) ? xin : g_h1;
    float* dst = (mode == 0) ? g_y : (mode == 1) ? g_z : g_m;

    int tx = threadIdx.x, ty = threadIdx.y;

    float4 wr[16];
    const float4* wg = reinterpret_cast<const float4*>(W + tx * DD);
    #pragma unroll
    for (int i = 0; i < 16; i++) wr[i] = wg[i];

    __shared__ float hs[8][64];

    int ntiles = N_NODES / 8;
    for (int tile = blockIdx.x; tile < ntiles; tile += gridDim.x) {
        int base = tile * 8;
        #pragma unroll
        for (int r = 0; r < 2; r++) {
            int node = base + ty + r * 4;
            hs[ty + r * 4][tx] = src[node * DD + tx];
        }
        __syncthreads();

        const float4* h0 = reinterpret_cast<const float4*>(&hs[ty][0]);
        const float4* h1 = reinterpret_cast<const float4*>(&hs[ty + 4][0]);
        float acc0 = 0.f, acc1 = 0.f;
        #pragma unroll
        for (int kk = 0; kk < 16; kk++) {
            float4 w = wr[kk];
            float4 a = h0[kk];
            float4 b = h1[kk];
            acc0 = fmaf(a.x, w.x, acc0); acc1 = fmaf(b.x, w.x, acc1);
            acc0 = fmaf(a.y, w.y, acc0); acc1 = fmaf(b.y, w.y, acc1);
            acc0 = fmaf(a.z, w.z, acc0); acc1 = fmaf(b.z, w.z, acc1);
            acc0 = fmaf(a.w, w.w, acc0); acc1 = fmaf(b.w, w.w, acc1);
        }
        dst[(base + ty) * DD + tx]     = acc0;
        dst[(base + ty + 4) * DD + tx] = acc1;
        __syncthreads();
    }
}

// ---------------------------------------------------------------------------
// Gather 1 (transform-first layer 1): g_h1 = relu(agg(g_y) + (1+eps0)*g_y).
// One warp per node, 12500 blocks for latency hiding. Atomic-free.
// ---------------------------------------------------------------------------
__global__ void __launch_bounds__(256) gather1_kernel(
        const float* __restrict__ eps0p) {
    int node = (blockIdx.x * blockDim.x + threadIdx.x) >> 5;
    if (node >= N_NODES) return;
    int lane = threadIdx.x & 31;
    int half = lane >> 4;
    int c = (lane & 15) << 2;

    int s = g_row[node], e = g_row[node + 1];

    float4 acc = make_float4(0.f, 0.f, 0.f, 0.f);
    for (int j = s + half; j < e; j += 2) {
        int src = __ldg(&g_srcp[j]);
        float4 v = *reinterpret_cast<const float4*>(g_y + src * DD + c);
        acc.x += v.x; acc.y += v.y; acc.z += v.z; acc.w += v.w;
    }
    const unsigned m = 0xffffffffu;
    acc.x += __shfl_xor_sync(m, acc.x, 16);
    acc.y += __shfl_xor_sync(m, acc.y, 16);
    acc.z += __shfl_xor_sync(m, acc.z, 16);
    acc.w += __shfl_xor_sync(m, acc.w, 16);
    if (half == 0) {
        float se = 1.0f + *eps0p;
        float4 yv = *reinterpret_cast<const float4*>(g_y + node * DD + c);
        float4 r;
        r.x = fmaxf(acc.x + se * yv.x, 0.f);
        r.y = fmaxf(acc.y + se * yv.y, 0.f);
        r.z = fmaxf(acc.z + se * yv.z, 0.f);
        r.w = fmaxf(acc.w + se * yv.w, 0.f);
        *reinterpret_cast<float4*>(g_h1 + node * DD + c) = r;
    }
}

// ---------------------------------------------------------------------------
// Gather 2 (transform-first layer 2 + final mix):
// out = 0.5 * ( g_m + relu(agg(g_z) + (1+eps1)*g_z) )
// ---------------------------------------------------------------------------
__global__ void __launch_bounds__(256) gather2_kernel(
        const float* __restrict__ eps1p,
        float* __restrict__ out) {
    int node = (blockIdx.x * blockDim.x + threadIdx.x) >> 5;
    if (node >= N_NODES) return;
    int lane = threadIdx.x & 31;
    int half = lane >> 4;
    int c = (lane & 15) << 2;

    int s = g_row[node], e = g_row[node + 1];

    float4 acc = make_float4(0.f, 0.f, 0.f, 0.f);
    for (int j = s + half; j < e; j += 2) {
        int src = __ldg(&g_srcp[j]);
        float4 v = *reinterpret_cast<const float4*>(g_z + src * DD + c);
        acc.x += v.x; acc.y += v.y; acc.z += v.z; acc.w += v.w;
    }
    const unsigned m = 0xffffffffu;
    acc.x += __shfl_xor_sync(m, acc.x, 16);
    acc.y += __shfl_xor_sync(m, acc.y, 16);
    acc.z += __shfl_xor_sync(m, acc.z, 16);
    acc.w += __shfl_xor_sync(m, acc.w, 16);
    if (half == 0) {
        float se = 1.0f + *eps1p;
        float4 zv = *reinterpret_cast<const float4*>(g_z + node * DD + c);
        float4 mv = *reinterpret_cast<const float4*>(g_m + node * DD + c);
        float4 r;
        r.x = 0.5f * (mv.x + fmaxf(acc.x + se * zv.x, 0.f));
        r.y = 0.5f * (mv.y + fmaxf(acc.y + se * zv.y, 0.f));
        r.z = 0.5f * (mv.z + fmaxf(acc.z + se * zv.z, 0.f));
        r.w = 0.5f * (mv.w + fmaxf(acc.w + se * zv.w, 0.f));
        *reinterpret_cast<float4*>(out + node * DD + c) = r;
    }
}

// ---------------------------------------------------------------------------
// Launch
// ---------------------------------------------------------------------------
extern "C" void kernel_launch(void* const* d_in, const int* in_sizes, int n_in,
                              void* d_out, int out_size) {
    const float* x    = (const float*)d_in[0];
    const void*  ei   = d_in[1];
    const float* W0   = (const float*)d_in[2];
    const float* eps0 = (const float*)d_in[3];
    const float* W1   = (const float*)d_in[4];
    const float* eps1 = (const float*)d_in[5];
    const float* Wm   = (const float*)d_in[6];
    float*       out  = (float*)d_out;

    dim3 gemm_block(64, 4);

    detect_dtype_kernel<<<1, 256>>>((const int*)ei);

    // y = x @ W0^T (independent of CSR build)
    gemm_kernel<<<1184, gemm_block>>>(x, W0, 0);

    // CSR build (once; reused by both layers)
    zero_cur_kernel<<<(N_NODES + 255) / 256, 256>>>();
    hist_kernel<<<E_EDGES / 256, 256>>>(ei);
    scan1_kernel<<<SCAN_BLOCKS, 256>>>();
    scan2_kernel<<<1, 128>>>();
    scan3_kernel<<<SCAN_BLOCKS, 256>>>();
    permute_kernel<<<E_EDGES / 256, 256>>>(ei);

    // Layer 1: h1 = relu(agg(y) + (1+eps0) y)
    gather1_kernel<<<(N_NODES * 32) / 256, 256>>>(eps0);

    // Layer 2 transforms
    gemm_kernel<<<1184, gemm_block>>>(x, W1, 1);
    gemm_kernel<<<1184, gemm_block>>>(x, Wm, 2);

    // Layer 2 aggregation + final mix
    gather2_kernel<<<(N_NODES * 32) / 256, 256>>>(eps1, out);
}